// round 6
// baseline (speedup 1.0000x reference)
#include <cuda_runtime.h>
#include <cuda_bf16.h>
#include <math_constants.h>
#include <cstdint>

// Problem constants
#define BATCH 4
#define SLEN  32768
#define C1    128
#define C2    256
#define HID   512
#define L1LEN 16384
#define L2LEN 8192
#define L3LEN 4096
#define VOCAB 2048
#define KCB   4

// ------------------- device scratch (device-code references ONLY) -------------------
__device__ __align__(16) float g_conv1[BATCH * C1 * L1LEN];
__device__ __align__(16) float g_conv2[BATCH * C2 * L2LEN];
__device__ __align__(16) float g_feats[BATCH * L3LEN * HID];   // fp32 exact (rescore)
__device__ __align__(16) __nv_bfloat16 g_fhi[BATCH * L3LEN * HID];
__device__ __align__(16) __nv_bfloat16 g_flo[BATCH * L3LEN * HID];
__device__ __align__(16) __nv_bfloat16 g_chi[KCB * VOCAB * HID];
__device__ __align__(16) __nv_bfloat16 g_clo[KCB * VOCAB * HID];
__device__ float g_c2[KCB * VOCAB];
__device__ int   g_tokens[BATCH * KCB * L3LEN];
__device__ int   g_cand[BATCH * KCB * L3LEN];
__device__ int   g_ncand;

// ==================== conv stack (fp32, unchanged from passing R3) ====================
__global__ void conv1_kernel(const float* __restrict__ x,
                             const float* __restrict__ w,
                             const float* __restrict__ bias) {
    int idx = blockIdx.x * blockDim.x + threadIdx.x;
    int l = idx & (L1LEN - 1);
    int c = (idx >> 14) & (C1 - 1);
    int b = idx >> 21;
    const float* xb = x + (size_t)b * SLEN;
    float acc = bias[c];
    int base = 2 * l - 3;
#pragma unroll
    for (int t = 0; t < 7; t++) {
        int p = base + t;
        float xv = (p >= 0 && p < SLEN) ? __ldg(xb + p) : 0.f;
        acc = fmaf(__ldg(w + c * 7 + t), xv, acc);
    }
    g_conv1[idx] = fmaxf(acc, 0.f);
}

template <int CI, int CO, int LOUT, bool RELU, bool TRANS_OUT, int STAGE>
__global__ void conv_tiled_kernel(const float* __restrict__ w,
                                  const float* __restrict__ bias) {
    const float* in  = (STAGE == 2) ? g_conv1 : g_conv2;
    float*       out = (STAGE == 2) ? g_conv2 : g_feats;

    const int LIN = 2 * LOUT;
    __shared__ float in_s[8][72];
    __shared__ float w_s[8 * 7 * 32];

    int tid = threadIdx.x;
    int l0  = blockIdx.x * 32;
    int co0 = blockIdx.y * 32;
    int b   = blockIdx.z;
    int co  = tid & 31;
    int lg  = tid >> 5;

    float acc[8];
#pragma unroll
    for (int j = 0; j < 8; j++) acc[j] = 0.f;

    for (int ci0 = 0; ci0 < CI; ci0 += 8) {
        __syncthreads();
        for (int i = tid; i < 8 * 70; i += 128) {
            int ci = i / 70, p = i % 70;
            int pg = 2 * l0 - 3 + p;
            float v = 0.f;
            if (p < 69 && pg >= 0 && pg < LIN)
                v = in[((size_t)b * CI + ci0 + ci) * LIN + pg];
            in_s[ci][p] = v;
        }
        for (int i = tid; i < 8 * 7 * 32; i += 128) {
            int co_i = i & 31;
            int rest = i >> 5;
            int t = rest % 7, ci = rest / 7;
            w_s[rest * 32 + co_i] = w[((size_t)(co0 + co_i) * CI + ci0 + ci) * 7 + t];
        }
        __syncthreads();

#pragma unroll
        for (int ci = 0; ci < 8; ci++) {
            float xv[21];
#pragma unroll
            for (int p = 0; p < 21; p++) xv[p] = in_s[ci][16 * lg + p];
#pragma unroll
            for (int t = 0; t < 7; t++) {
                float wv = w_s[(ci * 7 + t) * 32 + co];
#pragma unroll
                for (int j = 0; j < 8; j++)
                    acc[j] = fmaf(wv, xv[2 * j + t], acc[j]);
            }
        }
    }

    float bv = bias[co0 + co];
#pragma unroll
    for (int j = 0; j < 8; j++) {
        float r = acc[j] + bv;
        if (RELU) r = fmaxf(r, 0.f);
        int l = l0 + lg * 8 + j;
        if (TRANS_OUT)
            out[((size_t)b * LOUT + l) * CO + co0 + co] = r;
        else
            out[((size_t)b * CO + co0 + co) * LOUT + l] = r;
    }
}

// ==================== bf16 hi/lo splits ====================
__global__ void split_feats_kernel() {
    int i = blockIdx.x * blockDim.x + threadIdx.x;
    if (i >= BATCH * L3LEN * HID) return;
    float x = g_feats[i];
    __nv_bfloat16 hi = __float2bfloat16_rn(x);
    g_fhi[i] = hi;
    g_flo[i] = __float2bfloat16_rn(x - __bfloat162float(hi));
}
__global__ void split_cb_kernel(const float* __restrict__ cb) {
    int i = blockIdx.x * blockDim.x + threadIdx.x;
    if (i >= KCB * VOCAB * HID) return;
    float x = cb[i];
    __nv_bfloat16 hi = __float2bfloat16_rn(x);
    g_chi[i] = hi;
    g_clo[i] = __float2bfloat16_rn(x - __bfloat162float(hi));
}

// ==================== c2 ====================
__global__ void c2_kernel(const float* __restrict__ cb) {
    int row = blockIdx.x * 8 + (threadIdx.x >> 5);
    int lane = threadIdx.x & 31;
    const float* p = cb + (size_t)row * HID;
    float s = 0.f;
#pragma unroll 4
    for (int h = lane; h < HID; h += 32) {
        float v = p[h];
        s = fmaf(v, v, s);
    }
#pragma unroll
    for (int off = 16; off; off >>= 1)
        s += __shfl_xor_sync(0xffffffffu, s, off);
    if (lane == 0) g_c2[row] = s;
}

__global__ void zero_cand_kernel() { g_ncand = 0; }

// ==================== mma.sync bf16-split argmin ====================
// Block 256 thr = 8 warps (wm 0..1 x wn 0..3). Block tile: 64 l x 256 v per vb step.
// Warp tile: m=32, n=64. K streamed in chunks of 64. Rows padded to 144B.
// CROSS-WARP: each wn warp covers a distinct 64-v slice -> partial (min,min2,idx)
// reduced through SMEM across the 4 wn warps before tokens are written.

#define OFF_AHI  0
#define OFF_ALO  (64 * 144)                    //  9216
#define OFF_BHI  (2 * 64 * 144)                // 18432
#define OFF_BLO  (OFF_BHI + 256 * 144)         // 55296
#define OFF_C2S  (OFF_BLO + 256 * 144)         // 92160
#define OFF_RED  (OFF_C2S + 1024)              // 93184: [64][4] x {v,2,i}
#define MS_TOTAL (OFF_RED + 64 * 4 * 12)       // 96256

#define AMB_MARGIN 0.125f

__device__ __forceinline__ void mma_bf16(float* c, const uint32_t* a, const uint32_t* b) {
    asm volatile(
        "mma.sync.aligned.m16n8k16.row.col.f32.bf16.bf16.f32 "
        "{%0,%1,%2,%3}, {%4,%5,%6,%7}, {%8,%9}, {%0,%1,%2,%3};"
        : "+f"(c[0]), "+f"(c[1]), "+f"(c[2]), "+f"(c[3])
        : "r"(a[0]), "r"(a[1]), "r"(a[2]), "r"(a[3]), "r"(b[0]), "r"(b[1]));
}

__device__ __forceinline__ void upd_min(float& m, float& m2, int& idx, float d, int v) {
    if (d < m)       { m2 = m; m = d; idx = v; }
    else if (d < m2) { m2 = d; }
}
__device__ __forceinline__ void merge_min(float& m, float& m2, int& idx,
                                          float om, float om2, int oidx) {
    if (om < m) { m2 = fminf(m, om2); m = om; idx = oidx; }
    else        { m2 = fminf(m2, om); }
}

__global__ __launch_bounds__(256, 2) void argmin_mma_kernel() {
    extern __shared__ char smem[];
    char* Ah = smem + OFF_AHI;
    char* Al = smem + OFF_ALO;
    char* Bh = smem + OFF_BHI;
    char* Bl = smem + OFF_BLO;
    float* c2_s = (float*)(smem + OFF_C2S);
    float* red_v = (float*)(smem + OFF_RED);             // [64][4]
    float* red_2 = (float*)(smem + OFF_RED + 1024);      // [64][4]
    int*   red_i = (int*)  (smem + OFF_RED + 2048);      // [64][4]

    int tid = threadIdx.x;
    int wid = tid >> 5, lane = tid & 31;
    int wm = wid >> 2, wn = wid & 3;
    int g = lane >> 2, t = lane & 3;

    int l0 = blockIdx.x * 64, k = blockIdx.y, b = blockIdx.z;

    const __nv_bfloat16* Ahi_g = g_fhi + ((size_t)b * L3LEN + l0) * HID;
    const __nv_bfloat16* Alo_g = g_flo + ((size_t)b * L3LEN + l0) * HID;
    const __nv_bfloat16* Bhi_g = g_chi + (size_t)k * VOCAB * HID;
    const __nv_bfloat16* Blo_g = g_clo + (size_t)k * VOCAB * HID;

    float minv[4], min2[4];
    int   mini[4];
#pragma unroll
    for (int i = 0; i < 4; i++) { minv[i] = CUDART_INF_F; min2[i] = CUDART_INF_F; mini[i] = 0; }

    for (int vb = 0; vb < 8; vb++) {
        float acc[2][8][4];
#pragma unroll
        for (int mi = 0; mi < 2; mi++)
#pragma unroll
            for (int ni = 0; ni < 8; ni++)
#pragma unroll
                for (int j = 0; j < 4; j++) acc[mi][ni][j] = 0.f;

        for (int kc = 0; kc < 8; kc++) {
            __syncthreads();
            // A tile: 64 rows x 64 bf16 (hi+lo)
            for (int i = tid; i < 512; i += 256) {
                int r = i >> 3, q = i & 7;
                size_t gi = (size_t)r * HID + kc * 64 + q * 8;
                *(int4*)(Ah + r * 144 + q * 16) = *(const int4*)(Ahi_g + gi);
                *(int4*)(Al + r * 144 + q * 16) = *(const int4*)(Alo_g + gi);
            }
            // B tile: 256 rows x 64 bf16 (hi+lo)
            for (int i = tid; i < 2048; i += 256) {
                int r = i >> 3, q = i & 7;
                size_t gi = (size_t)(vb * 256 + r) * HID + kc * 64 + q * 8;
                *(int4*)(Bh + r * 144 + q * 16) = *(const int4*)(Bhi_g + gi);
                *(int4*)(Bl + r * 144 + q * 16) = *(const int4*)(Blo_g + gi);
            }
            __syncthreads();

#pragma unroll
            for (int ks = 0; ks < 4; ks++) {
                int kb = ks * 32 + 4 * t;
                uint32_t a_hi[2][4], a_lo[2][4];
#pragma unroll
                for (int mi = 0; mi < 2; mi++) {
                    int r0 = wm * 32 + mi * 16 + g;
                    const char* ph = Ah + r0 * 144 + kb;
                    const char* pl = Al + r0 * 144 + kb;
                    a_hi[mi][0] = *(const uint32_t*)(ph);
                    a_hi[mi][1] = *(const uint32_t*)(ph + 8 * 144);
                    a_hi[mi][2] = *(const uint32_t*)(ph + 16);
                    a_hi[mi][3] = *(const uint32_t*)(ph + 8 * 144 + 16);
                    a_lo[mi][0] = *(const uint32_t*)(pl);
                    a_lo[mi][1] = *(const uint32_t*)(pl + 8 * 144);
                    a_lo[mi][2] = *(const uint32_t*)(pl + 16);
                    a_lo[mi][3] = *(const uint32_t*)(pl + 8 * 144 + 16);
                }
#pragma unroll
                for (int ni = 0; ni < 8; ni++) {
                    int vr = wn * 64 + ni * 8 + g;
                    const char* pb = Bh + vr * 144 + kb;
                    const char* pq = Bl + vr * 144 + kb;
                    uint32_t b_hi[2], b_lo[2];
                    b_hi[0] = *(const uint32_t*)(pb);
                    b_hi[1] = *(const uint32_t*)(pb + 16);
                    b_lo[0] = *(const uint32_t*)(pq);
                    b_lo[1] = *(const uint32_t*)(pq + 16);
#pragma unroll
                    for (int mi = 0; mi < 2; mi++) {
                        mma_bf16(acc[mi][ni], a_hi[mi], b_hi);
                        mma_bf16(acc[mi][ni], a_hi[mi], b_lo);
                        mma_bf16(acc[mi][ni], a_lo[mi], b_hi);
                    }
                }
            }
        }

        // epilogue: dist = c2 - 2*cross, per-row (min, min2) over this warp's v-slice
        __syncthreads();
        if (tid < 256) c2_s[tid] = g_c2[k * VOCAB + vb * 256 + tid];
        __syncthreads();

#pragma unroll
        for (int mi = 0; mi < 2; mi++) {
#pragma unroll
            for (int half = 0; half < 2; half++) {
                int ridx = mi * 2 + half;
#pragma unroll
                for (int ni = 0; ni < 8; ni++) {
#pragma unroll
                    for (int e = 0; e < 2; e++) {
                        int cl = wn * 64 + ni * 8 + 2 * t + e;
                        float dist = c2_s[cl] - 2.f * acc[mi][ni][half * 2 + e];
                        upd_min(minv[ridx], min2[ridx], mini[ridx],
                                dist, vb * 256 + cl);
                    }
                }
            }
        }
    }

    // reduce across the 4 lanes (t) sharing each row within the warp
#pragma unroll
    for (int off = 1; off <= 2; off <<= 1) {
#pragma unroll
        for (int i = 0; i < 4; i++) {
            float om  = __shfl_xor_sync(0xffffffffu, minv[i], off);
            float om2 = __shfl_xor_sync(0xffffffffu, min2[i], off);
            int   oi  = __shfl_xor_sync(0xffffffffu, mini[i], off);
            merge_min(minv[i], min2[i], mini[i], om, om2, oi);
        }
    }

    // deposit per-warp partials: row l_local in [0,64), slot wn
    __syncthreads();
    if (t == 0) {
#pragma unroll
        for (int mi = 0; mi < 2; mi++) {
#pragma unroll
            for (int half = 0; half < 2; half++) {
                int ridx = mi * 2 + half;
                int lloc = wm * 32 + mi * 16 + half * 8 + g;
                red_v[lloc * 4 + wn] = minv[ridx];
                red_2[lloc * 4 + wn] = min2[ridx];
                red_i[lloc * 4 + wn] = mini[ridx];
            }
        }
    }
    __syncthreads();

    // final cross-warp merge + write (threads 0..63, one per row)
    if (tid < 64) {
        float m  = red_v[tid * 4 + 0];
        float m2 = red_2[tid * 4 + 0];
        int   mi = red_i[tid * 4 + 0];
#pragma unroll
        for (int w = 1; w < 4; w++)
            merge_min(m, m2, mi, red_v[tid * 4 + w], red_2[tid * 4 + w], red_i[tid * 4 + w]);
        int code = ((b * KCB + k) * L3LEN) + l0 + tid;
        g_tokens[code] = mi;
        if (m2 - m < AMB_MARGIN) {
            int ci = atomicAdd(&g_ncand, 1);
            if (ci < BATCH * KCB * L3LEN) g_cand[ci] = code;
        }
    }
}

// ==================== exact fp32 rescore of ambiguous tokens ====================
__global__ void rescore_kernel(const float* __restrict__ cb) {
    __shared__ float red_v[256];
    __shared__ int   red_i[256];
    int n = g_ncand;
    if (n > BATCH * KCB * L3LEN) n = BATCH * KCB * L3LEN;
    for (int ci = blockIdx.x; ci < n; ci += gridDim.x) {
        int code = g_cand[ci];
        int l = code & (L3LEN - 1);
        int bk = code >> 12;
        int k = bk & (KCB - 1);
        int b = bk >> 2;
        const float* f = g_feats + ((size_t)b * L3LEN + l) * HID;
        const float* C = cb + (size_t)k * VOCAB * HID;
        float bestv = CUDART_INF_F;
        int besti = 0;
        for (int v = threadIdx.x; v < VOCAB; v += 256) {
            const float* c = C + (size_t)v * HID;
            float dot = 0.f;
#pragma unroll 8
            for (int h = 0; h < HID; h++) dot = fmaf(__ldg(f + h), __ldg(c + h), dot);
            float d = g_c2[k * VOCAB + v] - 2.f * dot;
            if (d < bestv) { bestv = d; besti = v; }
        }
        red_v[threadIdx.x] = bestv;
        red_i[threadIdx.x] = besti;
        __syncthreads();
        for (int s = 128; s; s >>= 1) {
            if (threadIdx.x < s) {
                float ov = red_v[threadIdx.x + s];
                int   oi = red_i[threadIdx.x + s];
                if (ov < red_v[threadIdx.x] ||
                    (ov == red_v[threadIdx.x] && oi < red_i[threadIdx.x])) {
                    red_v[threadIdx.x] = ov;
                    red_i[threadIdx.x] = oi;
                }
            }
            __syncthreads();
        }
        if (threadIdx.x == 0) g_tokens[code] = red_i[0];
        __syncthreads();
    }
}

// ==================== outputs ====================
__global__ void emb_kernel(const float* __restrict__ embedding, float* __restrict__ out) {
    int bl = blockIdx.x;
    int b = bl >> 12;
    int l = bl & (L3LEN - 1);
    int t0 = g_tokens[((size_t)b * KCB + 0) * L3LEN + l];
    int t1 = g_tokens[((size_t)b * KCB + 1) * L3LEN + l];
    int t2 = g_tokens[((size_t)b * KCB + 2) * L3LEN + l];
    int t3 = g_tokens[((size_t)b * KCB + 3) * L3LEN + l];
    const float4* e0 = (const float4*)(embedding + (size_t)t0 * HID);
    const float4* e1 = (const float4*)(embedding + (size_t)t1 * HID);
    const float4* e2 = (const float4*)(embedding + (size_t)t2 * HID);
    const float4* e3 = (const float4*)(embedding + (size_t)t3 * HID);
    int h = threadIdx.x;
    float4 v0 = e0[h], v1 = e1[h], v2 = e2[h], v3 = e3[h];
    float4 rr;
    rr.x = 0.25f * (v0.x + v1.x + v2.x + v3.x);
    rr.y = 0.25f * (v0.y + v1.y + v2.y + v3.y);
    rr.z = 0.25f * (v0.z + v1.z + v2.z + v3.z);
    rr.w = 0.25f * (v0.w + v1.w + v2.w + v3.w);
    ((float4*)(out + ((size_t)b * L3LEN + l) * HID))[h] = rr;
}

__global__ void tok2f_kernel(float* __restrict__ out) {
    int i = blockIdx.x * blockDim.x + threadIdx.x;
    if (i < BATCH * KCB * L3LEN) out[i] = (float)g_tokens[i];
}

// ==================== launch ====================
extern "C" void kernel_launch(void* const* d_in, const int* in_sizes, int n_in,
                              void* d_out, int out_size) {
    const float* audio = 0; const float* w1 = 0; const float* b1 = 0;
    const float* w2 = 0; const float* b2 = 0; const float* w3 = 0; const float* b3 = 0;
    const float* codebook = 0; const float* embedding = 0;
    for (int i = 0; i < n_in; i++) {
        const float* p = (const float*)d_in[i];
        switch (in_sizes[i]) {
            case BATCH * SLEN:      audio = p; break;
            case C1 * 1 * 7:        w1 = p; break;
            case C1:                b1 = p; break;
            case C2 * C1 * 7:       w2 = p; break;
            case C2:                b2 = p; break;
            case HID * C2 * 7:      w3 = p; break;
            case HID:               b3 = p; break;
            case KCB * VOCAB * HID: codebook = p; break;
            case VOCAB * HID:       embedding = p; break;
            default: break;
        }
    }

    cudaFuncSetAttribute(argmin_mma_kernel,
                         cudaFuncAttributeMaxDynamicSharedMemorySize, MS_TOTAL);

    // conv stack
    conv1_kernel<<<(BATCH * C1 * L1LEN) / 256, 256>>>(audio, w1, b1);
    {
        dim3 grid(L2LEN / 32, C2 / 32, BATCH);
        conv_tiled_kernel<C1, C2, L2LEN, true, false, 2><<<grid, 128>>>(w2, b2);
    }
    {
        dim3 grid(L3LEN / 32, HID / 32, BATCH);
        conv_tiled_kernel<C2, HID, L3LEN, false, true, 3><<<grid, 128>>>(w3, b3);
    }

    // splits + norms
    split_feats_kernel<<<(BATCH * L3LEN * HID) / 256, 256>>>();
    split_cb_kernel<<<(KCB * VOCAB * HID) / 256, 256>>>(codebook);
    c2_kernel<<<(KCB * VOCAB) / 8, 256>>>(codebook);
    zero_cand_kernel<<<1, 1>>>();

    // tensor-core argmin + exact rescore
    {
        dim3 grid(L3LEN / 64, KCB, BATCH);
        argmin_mma_kernel<<<grid, 256, MS_TOTAL>>>();
    }
    rescore_kernel<<<1024, 256>>>(codebook);

    // outputs: tokens (as float) then emb
    const int TOK = BATCH * KCB * L3LEN;
    const int EMB = BATCH * L3LEN * HID;
    float* out = (float*)d_out;
    if (out_size >= TOK + EMB) {
        tok2f_kernel<<<(TOK + 255) / 256, 256>>>(out);
        emb_kernel<<<BATCH * L3LEN, 128>>>(embedding, out + TOK);
    } else if (out_size >= EMB) {
        emb_kernel<<<BATCH * L3LEN, 128>>>(embedding, out);
    } else {
        tok2f_kernel<<<(TOK + 255) / 256, 256>>>(out);
    }
}

// round 7
// speedup vs baseline: 1.9477x; 1.9477x over previous
#include <cuda_runtime.h>
#include <cuda_bf16.h>
#include <cuda_fp16.h>
#include <math_constants.h>
#include <cstdint>

// Problem constants
#define BATCH 4
#define SLEN  32768
#define C1    128
#define C2    256
#define HID   512
#define L1LEN 16384
#define L2LEN 8192
#define L3LEN 4096
#define VOCAB 2048
#define KCB   4
#define NTOK  (BATCH * KCB * L3LEN)      // 65536

// ------------------- device scratch (device-code references ONLY) -------------------
__device__ __align__(16) float g_conv1[BATCH * C1 * L1LEN];
__device__ __align__(16) float g_conv2[BATCH * C2 * L2LEN];
__device__ __align__(16) float g_feats[BATCH * L3LEN * HID];       // fp32 exact
__device__ __align__(16) __nv_bfloat16 g_fhi[BATCH * L3LEN * HID];
__device__ __align__(16) __nv_bfloat16 g_chi[KCB * VOCAB * HID];
__device__ __align__(16) __half g_cross[(size_t)NTOK * VOCAB];     // 256MB approx cross
__device__ float g_c2[KCB * VOCAB];
__device__ float g_cbmax[KCB];
__device__ int   g_tokens[NTOK];

// ==================== conv stack (fp32, unchanged from passing R3) ====================
__global__ void conv1_kernel(const float* __restrict__ x,
                             const float* __restrict__ w,
                             const float* __restrict__ bias) {
    int idx = blockIdx.x * blockDim.x + threadIdx.x;
    int l = idx & (L1LEN - 1);
    int c = (idx >> 14) & (C1 - 1);
    int b = idx >> 21;
    const float* xb = x + (size_t)b * SLEN;
    float acc = bias[c];
    int base = 2 * l - 3;
#pragma unroll
    for (int t = 0; t < 7; t++) {
        int p = base + t;
        float xv = (p >= 0 && p < SLEN) ? __ldg(xb + p) : 0.f;
        acc = fmaf(__ldg(w + c * 7 + t), xv, acc);
    }
    g_conv1[idx] = fmaxf(acc, 0.f);
}

template <int CI, int CO, int LOUT, bool RELU, bool TRANS_OUT, int STAGE>
__global__ void conv_tiled_kernel(const float* __restrict__ w,
                                  const float* __restrict__ bias) {
    const float* in  = (STAGE == 2) ? g_conv1 : g_conv2;
    float*       out = (STAGE == 2) ? g_conv2 : g_feats;

    const int LIN = 2 * LOUT;
    __shared__ float in_s[8][72];
    __shared__ float w_s[8 * 7 * 32];

    int tid = threadIdx.x;
    int l0  = blockIdx.x * 32;
    int co0 = blockIdx.y * 32;
    int b   = blockIdx.z;
    int co  = tid & 31;
    int lg  = tid >> 5;

    float acc[8];
#pragma unroll
    for (int j = 0; j < 8; j++) acc[j] = 0.f;

    for (int ci0 = 0; ci0 < CI; ci0 += 8) {
        __syncthreads();
        for (int i = tid; i < 8 * 70; i += 128) {
            int ci = i / 70, p = i % 70;
            int pg = 2 * l0 - 3 + p;
            float v = 0.f;
            if (p < 69 && pg >= 0 && pg < LIN)
                v = in[((size_t)b * CI + ci0 + ci) * LIN + pg];
            in_s[ci][p] = v;
        }
        for (int i = tid; i < 8 * 7 * 32; i += 128) {
            int co_i = i & 31;
            int rest = i >> 5;
            int t = rest % 7, ci = rest / 7;
            w_s[rest * 32 + co_i] = w[((size_t)(co0 + co_i) * CI + ci0 + ci) * 7 + t];
        }
        __syncthreads();

#pragma unroll
        for (int ci = 0; ci < 8; ci++) {
            float xv[21];
#pragma unroll
            for (int p = 0; p < 21; p++) xv[p] = in_s[ci][16 * lg + p];
#pragma unroll
            for (int t = 0; t < 7; t++) {
                float wv = w_s[(ci * 7 + t) * 32 + co];
#pragma unroll
                for (int j = 0; j < 8; j++)
                    acc[j] = fmaf(wv, xv[2 * j + t], acc[j]);
            }
        }
    }

    float bv = bias[co0 + co];
#pragma unroll
    for (int j = 0; j < 8; j++) {
        float r = acc[j] + bv;
        if (RELU) r = fmaxf(r, 0.f);
        int l = l0 + lg * 8 + j;
        if (TRANS_OUT)
            out[((size_t)b * LOUT + l) * CO + co0 + co] = r;
        else
            out[((size_t)b * CO + co0 + co) * LOUT + l] = r;
    }
}

// ==================== bf16 hi conversions ====================
__global__ void split_feats_kernel() {
    int i = blockIdx.x * blockDim.x + threadIdx.x;
    if (i >= BATCH * L3LEN * HID) return;
    g_fhi[i] = __float2bfloat16_rn(g_feats[i]);
}
__global__ void split_cb_kernel(const float* __restrict__ cb) {
    int i = blockIdx.x * blockDim.x + threadIdx.x;
    if (i >= KCB * VOCAB * HID) return;
    g_chi[i] = __float2bfloat16_rn(cb[i]);
}

// ==================== c2 + per-codebook max norm ====================
__global__ void c2_kernel(const float* __restrict__ cb) {
    int row = blockIdx.x * 8 + (threadIdx.x >> 5);
    int lane = threadIdx.x & 31;
    const float* p = cb + (size_t)row * HID;
    float s = 0.f;
#pragma unroll 4
    for (int h = lane; h < HID; h += 32) {
        float v = p[h];
        s = fmaf(v, v, s);
    }
#pragma unroll
    for (int off = 16; off; off >>= 1)
        s += __shfl_xor_sync(0xffffffffu, s, off);
    if (lane == 0) g_c2[row] = s;
}

__global__ void cbmax_kernel() {
    __shared__ float red[256];
    int k = blockIdx.x;
    float m = 0.f;
    for (int v = threadIdx.x; v < VOCAB; v += 256)
        m = fmaxf(m, g_c2[k * VOCAB + v]);
    red[threadIdx.x] = m;
    __syncthreads();
    for (int s = 128; s; s >>= 1) {
        if (threadIdx.x < s) red[threadIdx.x] = fmaxf(red[threadIdx.x], red[threadIdx.x + s]);
        __syncthreads();
    }
    if (threadIdx.x == 0) g_cbmax[k] = sqrtf(red[0]);
}

// ==================== stage 1: pure bf16 hi GEMM -> fp16 cross ====================
// Block 256 thr = 8 warps (wm 0..1 x wn 0..3). Block tile 128 l x 256 v, full K=512.
// Warp tile 64x64. K chunks of 64 bf16, double-buffered via cp.async.
#define ST_A 0
#define ST_B 18432
#define ST_STRIDE 55296        // A(128x144) + B(256x144)
#define ST_TOTAL 110592

__device__ __forceinline__ uint32_t smem_u32(const void* p) {
    uint32_t a;
    asm("{ .reg .u64 t; cvta.to.shared.u64 t, %1; cvt.u32.u64 %0, t; }" : "=r"(a) : "l"(p));
    return a;
}
__device__ __forceinline__ void cp_async16(uint32_t s, const void* g) {
    asm volatile("cp.async.cg.shared.global [%0], [%1], 16;" :: "r"(s), "l"(g) : "memory");
}
__device__ __forceinline__ void mma_bf16(float* c, const uint32_t* a, const uint32_t* b) {
    asm volatile(
        "mma.sync.aligned.m16n8k16.row.col.f32.bf16.bf16.f32 "
        "{%0,%1,%2,%3}, {%4,%5,%6,%7}, {%8,%9}, {%0,%1,%2,%3};"
        : "+f"(c[0]), "+f"(c[1]), "+f"(c[2]), "+f"(c[3])
        : "r"(a[0]), "r"(a[1]), "r"(a[2]), "r"(a[3]), "r"(b[0]), "r"(b[1]));
}

__global__ __launch_bounds__(256, 1) void gemm_hi_kernel() {
    extern __shared__ char smem[];
    uint32_t sbase = smem_u32(smem);

    const int tid = threadIdx.x;
    const int wid = tid >> 5, lane = tid & 31;
    const int wm = wid >> 2, wn = wid & 3;
    const int g = lane >> 2, t = lane & 3;
    const int lt = blockIdx.x;         // 32 l-tiles
    const int vt = blockIdx.y;         // 8 v-tiles
    const int bk = blockIdx.z;         // 16
    const int b = bk >> 2, k = bk & 3;

    const __nv_bfloat16* A  = g_fhi + ((size_t)b * L3LEN + lt * 128) * HID;
    const __nv_bfloat16* Bm = g_chi + ((size_t)k * VOCAB + vt * 256) * HID;

    auto load_chunk = [&](int kc, int s) {
        uint32_t st = sbase + s * ST_STRIDE;
#pragma unroll
        for (int j = 0; j < 12; j++) {
            int idx = tid + j * 256;           // 0..3071
            if (idx < 1024) {
                int r = idx >> 3, q = idx & 7;
                cp_async16(st + ST_A + r * 144 + q * 16,
                           A + (size_t)r * HID + kc * 64 + q * 8);
            } else {
                int i2 = idx - 1024;
                int r = i2 >> 3, q = i2 & 7;
                cp_async16(st + ST_B + r * 144 + q * 16,
                           Bm + (size_t)r * HID + kc * 64 + q * 8);
            }
        }
        asm volatile("cp.async.commit_group;" ::: "memory");
    };

    float acc[4][8][4];
#pragma unroll
    for (int mi = 0; mi < 4; mi++)
#pragma unroll
        for (int ni = 0; ni < 8; ni++)
#pragma unroll
            for (int j = 0; j < 4; j++) acc[mi][ni][j] = 0.f;

    load_chunk(0, 0);
    for (int kc = 0; kc < 8; kc++) {
        if (kc < 7) {
            load_chunk(kc + 1, (kc + 1) & 1);
            asm volatile("cp.async.wait_group 1;" ::: "memory");
        } else {
            asm volatile("cp.async.wait_group 0;" ::: "memory");
        }
        __syncthreads();
        const char* As = smem + (kc & 1) * ST_STRIDE + ST_A;
        const char* Bs = smem + (kc & 1) * ST_STRIDE + ST_B;
#pragma unroll
        for (int ks = 0; ks < 4; ks++) {
            int kb = ks * 32 + 4 * t;
            uint32_t af[4][4];
#pragma unroll
            for (int mi = 0; mi < 4; mi++) {
                const char* p = As + (wm * 64 + mi * 16 + g) * 144 + kb;
                af[mi][0] = *(const uint32_t*)(p);
                af[mi][1] = *(const uint32_t*)(p + 8 * 144);
                af[mi][2] = *(const uint32_t*)(p + 16);
                af[mi][3] = *(const uint32_t*)(p + 8 * 144 + 16);
            }
#pragma unroll
            for (int ni = 0; ni < 8; ni++) {
                const char* p = Bs + (wn * 64 + ni * 8 + g) * 144 + kb;
                uint32_t bf[2];
                bf[0] = *(const uint32_t*)(p);
                bf[1] = *(const uint32_t*)(p + 16);
#pragma unroll
                for (int mi = 0; mi < 4; mi++) mma_bf16(acc[mi][ni], af[mi], bf);
            }
        }
        __syncthreads();
    }

    // epilogue: store cross as fp16
#pragma unroll
    for (int mi = 0; mi < 4; mi++) {
        int row = lt * 128 + wm * 64 + mi * 16 + g;   // l in [0,4096)
        size_t code = (size_t)(b * KCB + k) * L3LEN + row;
        __half* out0 = g_cross + code * VOCAB;
        __half* out1 = g_cross + (code + 8) * VOCAB;
#pragma unroll
        for (int ni = 0; ni < 8; ni++) {
            int col = vt * 256 + wn * 64 + ni * 8 + 2 * t;
            *(__half2*)(out0 + col) = __floats2half2_rn(acc[mi][ni][0], acc[mi][ni][1]);
            *(__half2*)(out1 + col) = __floats2half2_rn(acc[mi][ni][2], acc[mi][ni][3]);
        }
    }
}

// ==================== stage 2: per-token select + bounded exact rescore ====================
__device__ __forceinline__ void upd_min(float& m, float& m2, int& idx, float d, int v) {
    if (d < m)       { m2 = m; m = d; idx = v; }
    else if (d < m2) { m2 = d; }
}
__device__ __forceinline__ void merge_min(float& m, float& m2, int& idx,
                                          float om, float om2, int oidx) {
    if (om < m) { m2 = fminf(m, om2); m = om; idx = oidx; }
    else        { m2 = fminf(m2, om); }
}

__global__ __launch_bounds__(256) void select_kernel(const float* __restrict__ cb) {
    __shared__ float c2_s[VOCAB];
    int tid = threadIdx.x;
    int wid = tid >> 5, lane = tid & 31;
    int code0 = blockIdx.x * 8;                 // 8 tokens per block, same (b,k)
    int k = (code0 >> 12) & (KCB - 1);

    for (int i = tid; i < VOCAB; i += 256)
        c2_s[i] = g_c2[k * VOCAB + i];
    __syncthreads();

    int code = code0 + wid;
    int l = code & (L3LEN - 1);
    int b = code >> 14;                          // code = ((b*4+k)*4096+l)
    const __half2* crow2 = (const __half2*)(g_cross + (size_t)code * VOCAB);

    // sweep approx distances
    float minv = CUDART_INF_F, min2 = CUDART_INF_F;
    int mini = 0;
#pragma unroll 4
    for (int i = 0; i < 32; i++) {
        __half2 h = crow2[i * 32 + lane];
        int v = i * 64 + lane * 2;
        float d0 = c2_s[v]     - 2.f * __low2float(h);
        float d1 = c2_s[v + 1] - 2.f * __high2float(h);
        upd_min(minv, min2, mini, d0, v);
        upd_min(minv, min2, mini, d1, v + 1);
    }
#pragma unroll
    for (int off = 16; off; off >>= 1) {
        float om  = __shfl_xor_sync(0xffffffffu, minv, off);
        float om2 = __shfl_xor_sync(0xffffffffu, min2, off);
        int   oi  = __shfl_xor_sync(0xffffffffu, mini, off);
        merge_min(minv, min2, mini, om, om2, oi);
    }

    // feature row + norm (for error bound)
    const float* f = g_feats + ((size_t)b * L3LEN + l) * HID;
    float fr[16];
    float n2 = 0.f;
#pragma unroll
    for (int j = 0; j < 16; j++) {
        fr[j] = f[j * 32 + lane];
        n2 = fmaf(fr[j], fr[j], n2);
    }
#pragma unroll
    for (int off = 16; off; off >>= 1)
        n2 += __shfl_xor_sync(0xffffffffu, n2, off);

    float TH = 0.009f * sqrtf(n2) * g_cbmax[k] + 1.0f;

    if (min2 - minv > TH) {
        if (lane == 0) g_tokens[code] = mini;
        return;
    }

    // ambiguous: exact fp32 rescore of all v with approx d <= min + TH
    float thr = minv + TH;
    float bestd = CUDART_INF_F;
    int besti = VOCAB;
    for (int i = 0; i < 32; i++) {
        __half2 h = crow2[i * 32 + lane];
        int v = i * 64 + lane * 2;
        float d0 = c2_s[v]     - 2.f * __low2float(h);
        float d1 = c2_s[v + 1] - 2.f * __high2float(h);
        unsigned m0 = __ballot_sync(0xffffffffu, d0 <= thr);
        unsigned m1 = __ballot_sync(0xffffffffu, d1 <= thr);
        while (m0 | m1) {
            int s0 = m0 ? (__ffs(m0) - 1) : 33;
            int s1 = m1 ? (__ffs(m1) - 1) : 33;
            int vc;
            if (s0 <= s1) { vc = i * 64 + s0 * 2;     m0 &= m0 - 1; }
            else          { vc = i * 64 + s1 * 2 + 1; m1 &= m1 - 1; }
            const float* c = cb + ((size_t)k * VOCAB + vc) * HID;
            float dot = 0.f;
#pragma unroll
            for (int j = 0; j < 16; j++)
                dot = fmaf(fr[j], c[j * 32 + lane], dot);
#pragma unroll
            for (int off = 16; off; off >>= 1)
                dot += __shfl_xor_sync(0xffffffffu, dot, off);
            float de = c2_s[vc] - 2.f * dot;
            if (de < bestd || (de == bestd && vc < besti)) { bestd = de; besti = vc; }
        }
    }
    if (lane == 0) g_tokens[code] = besti;
}

// ==================== outputs ====================
__global__ void emb_kernel(const float* __restrict__ embedding, float* __restrict__ out) {
    int bl = blockIdx.x;
    int b = bl >> 12;
    int l = bl & (L3LEN - 1);
    int t0 = g_tokens[((size_t)b * KCB + 0) * L3LEN + l];
    int t1 = g_tokens[((size_t)b * KCB + 1) * L3LEN + l];
    int t2 = g_tokens[((size_t)b * KCB + 2) * L3LEN + l];
    int t3 = g_tokens[((size_t)b * KCB + 3) * L3LEN + l];
    const float4* e0 = (const float4*)(embedding + (size_t)t0 * HID);
    const float4* e1 = (const float4*)(embedding + (size_t)t1 * HID);
    const float4* e2 = (const float4*)(embedding + (size_t)t2 * HID);
    const float4* e3 = (const float4*)(embedding + (size_t)t3 * HID);
    int h = threadIdx.x;
    float4 v0 = e0[h], v1 = e1[h], v2 = e2[h], v3 = e3[h];
    float4 rr;
    rr.x = 0.25f * (v0.x + v1.x + v2.x + v3.x);
    rr.y = 0.25f * (v0.y + v1.y + v2.y + v3.y);
    rr.z = 0.25f * (v0.z + v1.z + v2.z + v3.z);
    rr.w = 0.25f * (v0.w + v1.w + v2.w + v3.w);
    ((float4*)(out + ((size_t)b * L3LEN + l) * HID))[h] = rr;
}

__global__ void tok2f_kernel(float* __restrict__ out) {
    int i = blockIdx.x * blockDim.x + threadIdx.x;
    if (i < NTOK) out[i] = (float)g_tokens[i];
}

// ==================== launch ====================
extern "C" void kernel_launch(void* const* d_in, const int* in_sizes, int n_in,
                              void* d_out, int out_size) {
    const float* audio = 0; const float* w1 = 0; const float* b1 = 0;
    const float* w2 = 0; const float* b2 = 0; const float* w3 = 0; const float* b3 = 0;
    const float* codebook = 0; const float* embedding = 0;
    for (int i = 0; i < n_in; i++) {
        const float* p = (const float*)d_in[i];
        switch (in_sizes[i]) {
            case BATCH * SLEN:      audio = p; break;
            case C1 * 1 * 7:        w1 = p; break;
            case C1:                b1 = p; break;
            case C2 * C1 * 7:       w2 = p; break;
            case C2:                b2 = p; break;
            case HID * C2 * 7:      w3 = p; break;
            case HID:               b3 = p; break;
            case KCB * VOCAB * HID: codebook = p; break;
            case VOCAB * HID:       embedding = p; break;
            default: break;
        }
    }

    cudaFuncSetAttribute(gemm_hi_kernel,
                         cudaFuncAttributeMaxDynamicSharedMemorySize, ST_TOTAL);

    // (ordered so the 4th launch — the profiler's capture slot — is conv2)
    conv1_kernel<<<(BATCH * C1 * L1LEN) / 256, 256>>>(audio, w1, b1);
    split_cb_kernel<<<(KCB * VOCAB * HID) / 256, 256>>>(codebook);
    c2_kernel<<<(KCB * VOCAB) / 8, 256>>>(codebook);
    {
        dim3 grid(L2LEN / 32, C2 / 32, BATCH);
        conv_tiled_kernel<C1, C2, L2LEN, true, false, 2><<<grid, 128>>>(w2, b2);
    }
    {
        dim3 grid(L3LEN / 32, HID / 32, BATCH);
        conv_tiled_kernel<C2, HID, L3LEN, false, true, 3><<<grid, 128>>>(w3, b3);
    }
    cbmax_kernel<<<KCB, 256>>>();
    split_feats_kernel<<<(BATCH * L3LEN * HID) / 256, 256>>>();

    {
        dim3 grid(L3LEN / 128, VOCAB / 256, KCB * BATCH);
        gemm_hi_kernel<<<grid, 256, ST_TOTAL>>>();
    }
    select_kernel<<<NTOK / 8, 256>>>(codebook);

    const int TOK = NTOK;
    const int EMB = BATCH * L3LEN * HID;
    float* out = (float*)d_out;
    if (out_size >= TOK + EMB) {
        tok2f_kernel<<<(TOK + 255) / 256, 256>>>(out);
        emb_kernel<<<BATCH * L3LEN, 128>>>(embedding, out + TOK);
    } else if (out_size >= EMB) {
        emb_kernel<<<BATCH * L3LEN, 128>>>(embedding, out);
    } else {
        tok2f_kernel<<<(TOK + 255) / 256, 256>>>(out);
    }
}

// round 8
// speedup vs baseline: 3.6653x; 1.8818x over previous
#include <cuda_runtime.h>
#include <cuda_bf16.h>
#include <cuda_fp16.h>
#include <math_constants.h>
#include <cstdint>

// Problem constants
#define BATCH 4
#define SLEN  32768
#define C1    128
#define C2    256
#define HID   512
#define L1LEN 16384
#define L2LEN 8192
#define L3LEN 4096
#define VOCAB 2048
#define KCB   4
#define NTOK  (BATCH * KCB * L3LEN)      // 65536

// ------------------- device scratch (device-code references ONLY) -------------------
__device__ __align__(16) float g_conv1[BATCH * C1 * L1LEN];
__device__ __align__(16) float g_conv2[BATCH * C2 * L2LEN];
__device__ __align__(16) float g_feats[BATCH * L3LEN * HID];       // fp32 exact
__device__ __align__(16) float g_w2t[C2 * C1 * 7];                 // [(ci*7+t)][co]
__device__ __align__(16) float g_w3t[HID * C2 * 7];
__device__ __align__(16) __nv_bfloat16 g_fhi[BATCH * L3LEN * HID];
__device__ __align__(16) __nv_bfloat16 g_chi[KCB * VOCAB * HID];
__device__ __align__(16) __half g_cross[(size_t)NTOK * VOCAB];     // 256MB approx cross
__device__ float g_c2[KCB * VOCAB];
__device__ float g_cbmax[KCB];
__device__ int   g_tokens[NTOK];

// ==================== weight transpose: w[co][ci][7] -> wt[(ci*7+t)][co] ====================
template <int CI, int CO, int STAGE>
__global__ void wtrans_kernel(const float* __restrict__ w) {
    float* wt = (STAGE == 2) ? g_w2t : g_w3t;
    int i = blockIdx.x * 256 + threadIdx.x;
    if (i >= CI * CO * 7) return;
    int co = i % CO;
    int row = i / CO;                 // ci*7 + t
    int ci = row / 7, t = row % 7;
    wt[i] = w[((size_t)co * CI + ci) * 7 + t];
}

// ==================== conv1: Cin=1, tile 64 l x 128 c ====================
__global__ __launch_bounds__(256) void conv1_fast_kernel(const float* __restrict__ x,
                                                         const float* __restrict__ w,
                                                         const float* __restrict__ bias) {
    __shared__ float a_s[136];
    int tid = threadIdx.x;
    int lane = tid & 31, lg = tid >> 5;
    int l0 = blockIdx.x * 64;
    int b = blockIdx.y;

    for (int p = tid; p < 133; p += 256) {
        int pg = 2 * l0 - 3 + p;
        a_s[p] = (pg >= 0 && pg < SLEN) ? x[(size_t)b * SLEN + pg] : 0.f;
    }
    __syncthreads();

    float wr[4][7], bv[4];
#pragma unroll
    for (int c = 0; c < 4; c++) {
        int ch = lane + 32 * c;
        bv[c] = bias[ch];
#pragma unroll
        for (int t = 0; t < 7; t++) wr[c][t] = w[ch * 7 + t];
    }

    float xv[21];
#pragma unroll
    for (int p = 0; p < 21; p++) xv[p] = a_s[16 * lg + p];

    float acc[4][8];
#pragma unroll
    for (int c = 0; c < 4; c++)
#pragma unroll
        for (int j = 0; j < 8; j++) acc[c][j] = bv[c];
#pragma unroll
    for (int t = 0; t < 7; t++) {
#pragma unroll
        for (int j = 0; j < 8; j++) {
            float xx = xv[2 * j + t];
#pragma unroll
            for (int c = 0; c < 4; c++)
                acc[c][j] = fmaf(wr[c][t], xx, acc[c][j]);
        }
    }
#pragma unroll
    for (int c = 0; c < 4; c++) {
        int ch = lane + 32 * c;
#pragma unroll
        for (int j = 0; j < 8; j++) {
            int l = l0 + lg * 8 + j;
            g_conv1[((size_t)b * C1 + ch) * L1LEN + l] = fmaxf(acc[c][j], 0.f);
        }
    }
}

// ==================== conv2/3: tile 64 l x 128 co, thread 4co x 8l ====================
template <int CI, int CO, int LOUT, bool RELU, bool TRANS_OUT, int STAGE>
__global__ __launch_bounds__(256) void conv_fast_kernel(const float* __restrict__ bias) {
    const float* in  = (STAGE == 2) ? g_conv1 : g_conv2;
    const float* wT  = (STAGE == 2) ? g_w2t : g_w3t;
    float*       out = (STAGE == 2) ? g_conv2 : g_feats;

    const int LIN = 2 * LOUT;
    __shared__ float in_s[8][136];
    __shared__ float w_s[56 * 128];

    int tid = threadIdx.x;
    int lane = tid & 31, lg = tid >> 5;
    int l0  = blockIdx.x * 64;
    int co0 = blockIdx.y * 128;
    int b   = blockIdx.z;

    float acc[4][8];
#pragma unroll
    for (int c = 0; c < 4; c++)
#pragma unroll
        for (int j = 0; j < 8; j++) acc[c][j] = 0.f;

    for (int ci0 = 0; ci0 < CI; ci0 += 8) {
        __syncthreads();
        // input window: 8 ci x 133 positions
        for (int i = tid; i < 8 * 136; i += 256) {
            int ci = i / 136, p = i % 136;
            int pg = 2 * l0 - 3 + p;
            float v = 0.f;
            if (p < 133 && pg >= 0 && pg < LIN)
                v = in[((size_t)b * CI + ci0 + ci) * LIN + pg];
            in_s[ci][p] = v;
        }
        // weights: 56 rows (ci*7+t) x 128 co, coalesced from transposed layout
        for (int i = tid; i < 56 * 128; i += 256) {
            int row = i >> 7, c = i & 127;
            w_s[i] = wT[(size_t)(ci0 * 7 + row) * CO + co0 + c];
        }
        __syncthreads();

#pragma unroll
        for (int ci = 0; ci < 8; ci++) {
            float xv[21];
#pragma unroll
            for (int p = 0; p < 21; p++) xv[p] = in_s[ci][16 * lg + p];
#pragma unroll
            for (int t = 0; t < 7; t++) {
                const float* wrow = &w_s[(ci * 7 + t) * 128];
                float w0 = wrow[lane];
                float w1 = wrow[lane + 32];
                float w2 = wrow[lane + 64];
                float w3 = wrow[lane + 96];
#pragma unroll
                for (int j = 0; j < 8; j++) {
                    float xx = xv[2 * j + t];
                    acc[0][j] = fmaf(w0, xx, acc[0][j]);
                    acc[1][j] = fmaf(w1, xx, acc[1][j]);
                    acc[2][j] = fmaf(w2, xx, acc[2][j]);
                    acc[3][j] = fmaf(w3, xx, acc[3][j]);
                }
            }
        }
    }

#pragma unroll
    for (int c = 0; c < 4; c++) {
        int co = co0 + lane + 32 * c;
        float bv = bias[co];
#pragma unroll
        for (int j = 0; j < 8; j++) {
            float r = acc[c][j] + bv;
            if (RELU) r = fmaxf(r, 0.f);
            int l = l0 + lg * 8 + j;
            if (TRANS_OUT)
                out[((size_t)b * LOUT + l) * CO + co] = r;
            else
                out[((size_t)b * CO + co) * LOUT + l] = r;
        }
    }
}

// ==================== bf16 hi conversions ====================
__global__ void split_feats_kernel() {
    int i = blockIdx.x * blockDim.x + threadIdx.x;
    if (i >= BATCH * L3LEN * HID) return;
    g_fhi[i] = __float2bfloat16_rn(g_feats[i]);
}
__global__ void split_cb_kernel(const float* __restrict__ cb) {
    int i = blockIdx.x * blockDim.x + threadIdx.x;
    if (i >= KCB * VOCAB * HID) return;
    g_chi[i] = __float2bfloat16_rn(cb[i]);
}

// ==================== c2 + per-codebook max norm ====================
__global__ void c2_kernel(const float* __restrict__ cb) {
    int row = blockIdx.x * 8 + (threadIdx.x >> 5);
    int lane = threadIdx.x & 31;
    const float* p = cb + (size_t)row * HID;
    float s = 0.f;
#pragma unroll 4
    for (int h = lane; h < HID; h += 32) {
        float v = p[h];
        s = fmaf(v, v, s);
    }
#pragma unroll
    for (int off = 16; off; off >>= 1)
        s += __shfl_xor_sync(0xffffffffu, s, off);
    if (lane == 0) g_c2[row] = s;
}

__global__ void cbmax_kernel() {
    __shared__ float red[256];
    int k = blockIdx.x;
    float m = 0.f;
    for (int v = threadIdx.x; v < VOCAB; v += 256)
        m = fmaxf(m, g_c2[k * VOCAB + v]);
    red[threadIdx.x] = m;
    __syncthreads();
    for (int s = 128; s; s >>= 1) {
        if (threadIdx.x < s) red[threadIdx.x] = fmaxf(red[threadIdx.x], red[threadIdx.x + s]);
        __syncthreads();
    }
    if (threadIdx.x == 0) g_cbmax[k] = sqrtf(red[0]);
}

// ==================== stage 1: pure bf16 hi GEMM -> fp16 cross ====================
#define ST_A 0
#define ST_B 18432
#define ST_STRIDE 55296        // A(128x144) + B(256x144)
#define ST_TOTAL 110592

__device__ __forceinline__ uint32_t smem_u32(const void* p) {
    uint32_t a;
    asm("{ .reg .u64 t; cvta.to.shared.u64 t, %1; cvt.u32.u64 %0, t; }" : "=r"(a) : "l"(p));
    return a;
}
__device__ __forceinline__ void cp_async16(uint32_t s, const void* g) {
    asm volatile("cp.async.cg.shared.global [%0], [%1], 16;" :: "r"(s), "l"(g) : "memory");
}
__device__ __forceinline__ void mma_bf16(float* c, const uint32_t* a, const uint32_t* b) {
    asm volatile(
        "mma.sync.aligned.m16n8k16.row.col.f32.bf16.bf16.f32 "
        "{%0,%1,%2,%3}, {%4,%5,%6,%7}, {%8,%9}, {%0,%1,%2,%3};"
        : "+f"(c[0]), "+f"(c[1]), "+f"(c[2]), "+f"(c[3])
        : "r"(a[0]), "r"(a[1]), "r"(a[2]), "r"(a[3]), "r"(b[0]), "r"(b[1]));
}

__global__ __launch_bounds__(256, 1) void gemm_hi_kernel() {
    extern __shared__ char smem[];
    uint32_t sbase = smem_u32(smem);

    const int tid = threadIdx.x;
    const int wid = tid >> 5, lane = tid & 31;
    const int wm = wid >> 2, wn = wid & 3;
    const int g = lane >> 2, t = lane & 3;
    const int lt = blockIdx.x;
    const int vt = blockIdx.y;
    const int bk = blockIdx.z;
    const int b = bk >> 2, k = bk & 3;

    const __nv_bfloat16* A  = g_fhi + ((size_t)b * L3LEN + lt * 128) * HID;
    const __nv_bfloat16* Bm = g_chi + ((size_t)k * VOCAB + vt * 256) * HID;

    auto load_chunk = [&](int kc, int s) {
        uint32_t st = sbase + s * ST_STRIDE;
#pragma unroll
        for (int j = 0; j < 12; j++) {
            int idx = tid + j * 256;
            if (idx < 1024) {
                int r = idx >> 3, q = idx & 7;
                cp_async16(st + ST_A + r * 144 + q * 16,
                           A + (size_t)r * HID + kc * 64 + q * 8);
            } else {
                int i2 = idx - 1024;
                int r = i2 >> 3, q = i2 & 7;
                cp_async16(st + ST_B + r * 144 + q * 16,
                           Bm + (size_t)r * HID + kc * 64 + q * 8);
            }
        }
        asm volatile("cp.async.commit_group;" ::: "memory");
    };

    float acc[4][8][4];
#pragma unroll
    for (int mi = 0; mi < 4; mi++)
#pragma unroll
        for (int ni = 0; ni < 8; ni++)
#pragma unroll
            for (int j = 0; j < 4; j++) acc[mi][ni][j] = 0.f;

    load_chunk(0, 0);
    for (int kc = 0; kc < 8; kc++) {
        if (kc < 7) {
            load_chunk(kc + 1, (kc + 1) & 1);
            asm volatile("cp.async.wait_group 1;" ::: "memory");
        } else {
            asm volatile("cp.async.wait_group 0;" ::: "memory");
        }
        __syncthreads();
        const char* As = smem + (kc & 1) * ST_STRIDE + ST_A;
        const char* Bs = smem + (kc & 1) * ST_STRIDE + ST_B;
#pragma unroll
        for (int ks = 0; ks < 4; ks++) {
            int kb = ks * 32 + 4 * t;
            uint32_t af[4][4];
#pragma unroll
            for (int mi = 0; mi < 4; mi++) {
                const char* p = As + (wm * 64 + mi * 16 + g) * 144 + kb;
                af[mi][0] = *(const uint32_t*)(p);
                af[mi][1] = *(const uint32_t*)(p + 8 * 144);
                af[mi][2] = *(const uint32_t*)(p + 16);
                af[mi][3] = *(const uint32_t*)(p + 8 * 144 + 16);
            }
#pragma unroll
            for (int ni = 0; ni < 8; ni++) {
                const char* p = Bs + (wn * 64 + ni * 8 + g) * 144 + kb;
                uint32_t bf[2];
                bf[0] = *(const uint32_t*)(p);
                bf[1] = *(const uint32_t*)(p + 16);
#pragma unroll
                for (int mi = 0; mi < 4; mi++) mma_bf16(acc[mi][ni], af[mi], bf);
            }
        }
        __syncthreads();
    }

#pragma unroll
    for (int mi = 0; mi < 4; mi++) {
        int row = lt * 128 + wm * 64 + mi * 16 + g;
        size_t code = (size_t)(b * KCB + k) * L3LEN + row;
        __half* out0 = g_cross + code * VOCAB;
        __half* out1 = g_cross + (code + 8) * VOCAB;
#pragma unroll
        for (int ni = 0; ni < 8; ni++) {
            int col = vt * 256 + wn * 64 + ni * 8 + 2 * t;
            *(__half2*)(out0 + col) = __floats2half2_rn(acc[mi][ni][0], acc[mi][ni][1]);
            *(__half2*)(out1 + col) = __floats2half2_rn(acc[mi][ni][2], acc[mi][ni][3]);
        }
    }
}

// ==================== stage 2: per-token select + bounded exact rescore ====================
__device__ __forceinline__ void upd_min(float& m, float& m2, int& idx, float d, int v) {
    if (d < m)       { m2 = m; m = d; idx = v; }
    else if (d < m2) { m2 = d; }
}
__device__ __forceinline__ void merge_min(float& m, float& m2, int& idx,
                                          float om, float om2, int oidx) {
    if (om < m) { m2 = fminf(m, om2); m = om; idx = oidx; }
    else        { m2 = fminf(m2, om); }
}

__global__ __launch_bounds__(256) void select_kernel(const float* __restrict__ cb) {
    __shared__ float c2_s[VOCAB];
    int tid = threadIdx.x;
    int wid = tid >> 5, lane = tid & 31;
    int code0 = blockIdx.x * 8;
    int k = (code0 >> 12) & (KCB - 1);

    for (int i = tid; i < VOCAB; i += 256)
        c2_s[i] = g_c2[k * VOCAB + i];
    __syncthreads();

    int code = code0 + wid;
    int l = code & (L3LEN - 1);
    int b = code >> 14;
    const __half2* crow2 = (const __half2*)(g_cross + (size_t)code * VOCAB);

    float minv = CUDART_INF_F, min2 = CUDART_INF_F;
    int mini = 0;
#pragma unroll 4
    for (int i = 0; i < 32; i++) {
        __half2 h = crow2[i * 32 + lane];
        int v = i * 64 + lane * 2;
        float d0 = c2_s[v]     - 2.f * __low2float(h);
        float d1 = c2_s[v + 1] - 2.f * __high2float(h);
        upd_min(minv, min2, mini, d0, v);
        upd_min(minv, min2, mini, d1, v + 1);
    }
#pragma unroll
    for (int off = 16; off; off >>= 1) {
        float om  = __shfl_xor_sync(0xffffffffu, minv, off);
        float om2 = __shfl_xor_sync(0xffffffffu, min2, off);
        int   oi  = __shfl_xor_sync(0xffffffffu, mini, off);
        merge_min(minv, min2, mini, om, om2, oi);
    }

    const float* f = g_feats + ((size_t)b * L3LEN + l) * HID;
    float fr[16];
    float n2 = 0.f;
#pragma unroll
    for (int j = 0; j < 16; j++) {
        fr[j] = f[j * 32 + lane];
        n2 = fmaf(fr[j], fr[j], n2);
    }
#pragma unroll
    for (int off = 16; off; off >>= 1)
        n2 += __shfl_xor_sync(0xffffffffu, n2, off);

    float TH = 0.009f * sqrtf(n2) * g_cbmax[k] + 1.0f;

    if (min2 - minv > TH) {
        if (lane == 0) g_tokens[code] = mini;
        return;
    }

    float thr = minv + TH;
    float bestd = CUDART_INF_F;
    int besti = VOCAB;
    for (int i = 0; i < 32; i++) {
        __half2 h = crow2[i * 32 + lane];
        int v = i * 64 + lane * 2;
        float d0 = c2_s[v]     - 2.f * __low2float(h);
        float d1 = c2_s[v + 1] - 2.f * __high2float(h);
        unsigned m0 = __ballot_sync(0xffffffffu, d0 <= thr);
        unsigned m1 = __ballot_sync(0xffffffffu, d1 <= thr);
        while (m0 | m1) {
            int s0 = m0 ? (__ffs(m0) - 1) : 33;
            int s1 = m1 ? (__ffs(m1) - 1) : 33;
            int vc;
            if (s0 <= s1) { vc = i * 64 + s0 * 2;     m0 &= m0 - 1; }
            else          { vc = i * 64 + s1 * 2 + 1; m1 &= m1 - 1; }
            const float* c = cb + ((size_t)k * VOCAB + vc) * HID;
            float dot = 0.f;
#pragma unroll
            for (int j = 0; j < 16; j++)
                dot = fmaf(fr[j], c[j * 32 + lane], dot);
#pragma unroll
            for (int off = 16; off; off >>= 1)
                dot += __shfl_xor_sync(0xffffffffu, dot, off);
            float de = c2_s[vc] - 2.f * dot;
            if (de < bestd || (de == bestd && vc < besti)) { bestd = de; besti = vc; }
        }
    }
    if (lane == 0) g_tokens[code] = besti;
}

// ==================== outputs ====================
__global__ void emb_kernel(const float* __restrict__ embedding, float* __restrict__ out) {
    int bl = blockIdx.x;
    int b = bl >> 12;
    int l = bl & (L3LEN - 1);
    int t0 = g_tokens[((size_t)b * KCB + 0) * L3LEN + l];
    int t1 = g_tokens[((size_t)b * KCB + 1) * L3LEN + l];
    int t2 = g_tokens[((size_t)b * KCB + 2) * L3LEN + l];
    int t3 = g_tokens[((size_t)b * KCB + 3) * L3LEN + l];
    const float4* e0 = (const float4*)(embedding + (size_t)t0 * HID);
    const float4* e1 = (const float4*)(embedding + (size_t)t1 * HID);
    const float4* e2 = (const float4*)(embedding + (size_t)t2 * HID);
    const float4* e3 = (const float4*)(embedding + (size_t)t3 * HID);
    int h = threadIdx.x;
    float4 v0 = e0[h], v1 = e1[h], v2 = e2[h], v3 = e3[h];
    float4 rr;
    rr.x = 0.25f * (v0.x + v1.x + v2.x + v3.x);
    rr.y = 0.25f * (v0.y + v1.y + v2.y + v3.y);
    rr.z = 0.25f * (v0.z + v1.z + v2.z + v3.z);
    rr.w = 0.25f * (v0.w + v1.w + v2.w + v3.w);
    ((float4*)(out + ((size_t)b * L3LEN + l) * HID))[h] = rr;
}

__global__ void tok2f_kernel(float* __restrict__ out) {
    int i = blockIdx.x * blockDim.x + threadIdx.x;
    if (i < NTOK) out[i] = (float)g_tokens[i];
}

// ==================== launch ====================
extern "C" void kernel_launch(void* const* d_in, const int* in_sizes, int n_in,
                              void* d_out, int out_size) {
    const float* audio = 0; const float* w1 = 0; const float* b1 = 0;
    const float* w2 = 0; const float* b2 = 0; const float* w3 = 0; const float* b3 = 0;
    const float* codebook = 0; const float* embedding = 0;
    for (int i = 0; i < n_in; i++) {
        const float* p = (const float*)d_in[i];
        switch (in_sizes[i]) {
            case BATCH * SLEN:      audio = p; break;
            case C1 * 1 * 7:        w1 = p; break;
            case C1:                b1 = p; break;
            case C2 * C1 * 7:       w2 = p; break;
            case C2:                b2 = p; break;
            case HID * C2 * 7:      w3 = p; break;
            case HID:               b3 = p; break;
            case KCB * VOCAB * HID: codebook = p; break;
            case VOCAB * HID:       embedding = p; break;
            default: break;
        }
    }

    cudaFuncSetAttribute(gemm_hi_kernel,
                         cudaFuncAttributeMaxDynamicSharedMemorySize, ST_TOTAL);

    // weight transposes + codebook prep (independent, tiny)
    wtrans_kernel<C1, C2, 2><<<(C1 * C2 * 7 + 255) / 256, 256>>>(w2);
    wtrans_kernel<C2, HID, 3><<<(C2 * HID * 7 + 255) / 256, 256>>>(w3);
    split_cb_kernel<<<(KCB * VOCAB * HID) / 256, 256>>>(codebook);
    c2_kernel<<<(KCB * VOCAB) / 8, 256>>>(codebook);
    cbmax_kernel<<<KCB, 256>>>();

    // conv stack
    {
        dim3 grid(L1LEN / 64, BATCH);
        conv1_fast_kernel<<<grid, 256>>>(audio, w1, b1);
    }
    {
        dim3 grid(L2LEN / 64, C2 / 128, BATCH);
        conv_fast_kernel<C1, C2, L2LEN, true, false, 2><<<grid, 256>>>(b2);
    }
    {
        dim3 grid(L3LEN / 64, HID / 128, BATCH);
        conv_fast_kernel<C2, HID, L3LEN, false, true, 3><<<grid, 256>>>(b3);
    }
    split_feats_kernel<<<(BATCH * L3LEN * HID) / 256, 256>>>();

    {
        dim3 grid(L3LEN / 128, VOCAB / 256, KCB * BATCH);
        gemm_hi_kernel<<<grid, 256, ST_TOTAL>>>();
    }
    select_kernel<<<NTOK / 8, 256>>>(codebook);

    const int TOK = NTOK;
    const int EMB = BATCH * L3LEN * HID;
    float* out = (float*)d_out;
    if (out_size >= TOK + EMB) {
        tok2f_kernel<<<(TOK + 255) / 256, 256>>>(out);
        emb_kernel<<<BATCH * L3LEN, 128>>>(embedding, out + TOK);
    } else if (out_size >= EMB) {
        emb_kernel<<<BATCH * L3LEN, 128>>>(embedding, out);
    } else {
        tok2f_kernel<<<(TOK + 255) / 256, 256>>>(out);
    }
}